// round 1
// baseline (speedup 1.0000x reference)
#include <cuda_runtime.h>

#define Nn 10000
#define Ee 320000
#define EA (Ee + Nn)
#define HID 256

// ---------------- scratch (static device globals; no allocations) ----------
__device__ __align__(16) float g_xl[Nn * HID];
__device__ __align__(16) float g_xr[Nn * HID];
__device__ __align__(16) float g_h [Nn * HID];
__device__ __align__(16) float g_h2[Nn * HID];
__device__ float        g_logit[EA * 4];
__device__ unsigned int g_mx[Nn * 4];
__device__ float        g_den[Nn * 4];
__device__ float        g_deg[Nn];
__device__ float        g_loop[Nn];
__device__ float        g_plog[Nn * 4];
__device__ unsigned int g_gmax;
__device__ float        g_gsum;

// ---------------- helpers ---------------------------------------------------
__device__ __forceinline__ unsigned int fenc(float x) {
    unsigned int u = __float_as_uint(x);
    return (u & 0x80000000u) ? ~u : (u | 0x80000000u);
}
__device__ __forceinline__ float fdec(unsigned int e) {
    return __uint_as_float((e & 0x80000000u) ? (e & 0x7FFFFFFFu) : ~e);
}
__device__ __forceinline__ float lrelu(float x) { return x > 0.f ? x : 0.2f * x; }

__device__ __forceinline__ void red4(float* p, float a, float b, float c, float d) {
    asm volatile("red.global.add.v4.f32 [%0], {%1,%2,%3,%4};"
                 :: "l"(p), "f"(a), "f"(b), "f"(c), "f"(d) : "memory");
}

// ---------------- kernels ---------------------------------------------------

// degree + loop-attr sum
__global__ void k_deg(const int* __restrict__ ei, const float* __restrict__ eat) {
    int e = blockIdx.x * blockDim.x + threadIdx.x;
    if (e >= Ee) return;
    int d = ei[Ee + e];
    atomicAdd(&g_deg[d], 1.0f);
    atomicAdd(&g_loop[d], eat[e]);
}

__global__ void k_loopdiv() {
    int i = blockIdx.x * blockDim.x + threadIdx.x;
    if (i < Nn) g_loop[i] /= fmaxf(g_deg[i], 1.0f);
}

// conv1 linear: x [N,4] @ W [4,256] + b  -> g_xl / g_xr
__global__ void k_lin1(const float* __restrict__ x,
                       const float* __restrict__ Wl, const float* __restrict__ bl,
                       const float* __restrict__ Wr, const float* __restrict__ br) {
    int idx = blockIdx.x * blockDim.x + threadIdx.x;
    if (idx >= Nn * HID) return;
    int i = idx >> 8, j = idx & 255;
    float x0 = x[i * 4], x1 = x[i * 4 + 1], x2 = x[i * 4 + 2], x3 = x[i * 4 + 3];
    g_xl[idx] = x0 * Wl[j] + x1 * Wl[256 + j] + x2 * Wl[512 + j] + x3 * Wl[768 + j] + bl[j];
    g_xr[idx] = x0 * Wr[j] + x1 * Wr[256 + j] + x2 * Wr[512 + j] + x3 * Wr[768 + j] + br[j];
}

// conv1 per-edge logits (4 heads) + segment max.  One warp per edge.
__global__ void k_c1_logit(const int* __restrict__ ei, const float* __restrict__ eat,
                           const float* __restrict__ We, const float* __restrict__ att) {
    int e = (blockIdx.x * blockDim.x + threadIdx.x) >> 5;
    if (e >= EA) return;
    int lane = threadIdx.x & 31;
    int s, d; float ea;
    if (e < Ee) { s = ei[e]; d = ei[Ee + e]; ea = eat[e]; }
    else        { s = e - Ee; d = s; ea = g_loop[s]; }
    int c0 = lane * 8;
    float4 a0 = *(const float4*)&g_xl[s * HID + c0];
    float4 a1 = *(const float4*)&g_xl[s * HID + c0 + 4];
    float4 b0 = *(const float4*)&g_xr[d * HID + c0];
    float4 b1 = *(const float4*)&g_xr[d * HID + c0 + 4];
    float4 w0 = *(const float4*)&We[c0];
    float4 w1 = *(const float4*)&We[c0 + 4];
    float4 t0 = *(const float4*)&att[c0];
    float4 t1 = *(const float4*)&att[c0 + 4];
    float acc;
    acc  = lrelu(a0.x + b0.x + ea * w0.x) * t0.x;
    acc += lrelu(a0.y + b0.y + ea * w0.y) * t0.y;
    acc += lrelu(a0.z + b0.z + ea * w0.z) * t0.z;
    acc += lrelu(a0.w + b0.w + ea * w0.w) * t0.w;
    acc += lrelu(a1.x + b1.x + ea * w1.x) * t1.x;
    acc += lrelu(a1.y + b1.y + ea * w1.y) * t1.y;
    acc += lrelu(a1.z + b1.z + ea * w1.z) * t1.z;
    acc += lrelu(a1.w + b1.w + ea * w1.w) * t1.w;
    acc += __shfl_xor_sync(0xffffffffu, acc, 1);
    acc += __shfl_xor_sync(0xffffffffu, acc, 2);
    acc += __shfl_xor_sync(0xffffffffu, acc, 4);
    if ((lane & 7) == 0) {
        int h = lane >> 3;
        g_logit[e * 4 + h] = acc;
        atomicMax(&g_mx[d * 4 + h], fenc(acc));
    }
}

// conv1 exp + denominator
__global__ void k_c1_expsum(const int* __restrict__ ei) {
    int idx = blockIdx.x * blockDim.x + threadIdx.x;
    if (idx >= EA * 4) return;
    int e = idx >> 2, h = idx & 3;
    int d = (e < Ee) ? ei[Ee + e] : e - Ee;
    float ex = __expf(g_logit[idx] - fdec(g_mx[d * 4 + h]));
    g_logit[idx] = ex;
    atomicAdd(&g_den[d * 4 + h], ex);
}

// conv1 weighted scatter.  One warp per edge, vector atomics.
__global__ void k_c1_agg(const int* __restrict__ ei) {
    int e = (blockIdx.x * blockDim.x + threadIdx.x) >> 5;
    if (e >= EA) return;
    int lane = threadIdx.x & 31;
    int s, d;
    if (e < Ee) { s = ei[e]; d = ei[Ee + e]; }
    else        { s = e - Ee; d = s; }
    int c0 = lane * 8, h = lane >> 3;
    float alpha = g_logit[e * 4 + h] / g_den[d * 4 + h];
    float4 a0 = *(const float4*)&g_xl[s * HID + c0];
    float4 a1 = *(const float4*)&g_xl[s * HID + c0 + 4];
    red4(&g_h[d * HID + c0],     a0.x * alpha, a0.y * alpha, a0.z * alpha, a0.w * alpha);
    red4(&g_h[d * HID + c0 + 4], a1.x * alpha, a1.y * alpha, a1.z * alpha, a1.w * alpha);
}

// layernorm(in + bias) * g + b, then relu.  One warp per node, in place ok.
__global__ void k_ln_relu(const float* __restrict__ inp, float* __restrict__ outp,
                          const float* __restrict__ bias, const float* __restrict__ gam,
                          const float* __restrict__ bet) {
    int w = (blockIdx.x * blockDim.x + threadIdx.x) >> 5;
    if (w >= Nn) return;
    int lane = threadIdx.x & 31, c0 = lane * 8;
    float v[8];
    float4 p0 = *(const float4*)&inp[w * HID + c0];
    float4 p1 = *(const float4*)&inp[w * HID + c0 + 4];
    float4 q0 = *(const float4*)&bias[c0];
    float4 q1 = *(const float4*)&bias[c0 + 4];
    v[0] = p0.x + q0.x; v[1] = p0.y + q0.y; v[2] = p0.z + q0.z; v[3] = p0.w + q0.w;
    v[4] = p1.x + q1.x; v[5] = p1.y + q1.y; v[6] = p1.z + q1.z; v[7] = p1.w + q1.w;
    float s = 0.f;
    #pragma unroll
    for (int k = 0; k < 8; k++) s += v[k];
    #pragma unroll
    for (int off = 16; off; off >>= 1) s += __shfl_xor_sync(0xffffffffu, s, off);
    float mu = s * (1.0f / HID);
    float q = 0.f;
    #pragma unroll
    for (int k = 0; k < 8; k++) { float t = v[k] - mu; q += t * t; }
    #pragma unroll
    for (int off = 16; off; off >>= 1) q += __shfl_xor_sync(0xffffffffu, q, off);
    float r = rsqrtf(q * (1.0f / HID) + 1e-5f);
    float4 go0 = *(const float4*)&gam[c0];
    float4 go1 = *(const float4*)&gam[c0 + 4];
    float4 bo0 = *(const float4*)&bet[c0];
    float4 bo1 = *(const float4*)&bet[c0 + 4];
    float4 o0, o1;
    o0.x = fmaxf((v[0] - mu) * r * go0.x + bo0.x, 0.f);
    o0.y = fmaxf((v[1] - mu) * r * go0.y + bo0.y, 0.f);
    o0.z = fmaxf((v[2] - mu) * r * go0.z + bo0.z, 0.f);
    o0.w = fmaxf((v[3] - mu) * r * go0.w + bo0.w, 0.f);
    o1.x = fmaxf((v[4] - mu) * r * go1.x + bo1.x, 0.f);
    o1.y = fmaxf((v[5] - mu) * r * go1.y + bo1.y, 0.f);
    o1.z = fmaxf((v[6] - mu) * r * go1.z + bo1.z, 0.f);
    o1.w = fmaxf((v[7] - mu) * r * go1.w + bo1.w, 0.f);
    *(float4*)&outp[w * HID + c0]     = o0;
    *(float4*)&outp[w * HID + c0 + 4] = o1;
}

// conv2 linears: g_h [N,256] @ W [256,256] + b -> g_xl (y=0) / g_xr (y=1)
// 32-node tile, 256 threads, thread owns one output column, 32 accumulators.
__global__ void k_gemm(const float* __restrict__ Hin,
                       const float* __restrict__ W0, const float* __restrict__ b0,
                       const float* __restrict__ W1, const float* __restrict__ b1) {
    __shared__ float sh[32][HID];
    const float* W  = blockIdx.y ? W1 : W0;
    const float* bb = blockIdx.y ? b1 : b0;
    float* O        = blockIdx.y ? g_xr : g_xl;
    int i0 = blockIdx.x * 32;
    int t = threadIdx.x;
    for (int idx = t; idx < 32 * HID; idx += 256) {
        int r = idx >> 8, c = idx & 255;
        sh[r][c] = (i0 + r < Nn) ? Hin[(i0 + r) * HID + c] : 0.f;
    }
    __syncthreads();
    float acc[32];
    #pragma unroll
    for (int i = 0; i < 32; i++) acc[i] = 0.f;
    for (int k = 0; k < HID; k += 4) {
        float w0 = W[k * HID + t];
        float w1 = W[(k + 1) * HID + t];
        float w2 = W[(k + 2) * HID + t];
        float w3 = W[(k + 3) * HID + t];
        #pragma unroll
        for (int i = 0; i < 32; i++) {
            float4 hv = *(const float4*)&sh[i][k];
            acc[i] += hv.x * w0 + hv.y * w1 + hv.z * w2 + hv.w * w3;
        }
    }
    float bj = bb[t];
    #pragma unroll
    for (int i = 0; i < 32; i++)
        if (i0 + i < Nn) O[(i0 + i) * HID + t] = acc[i] + bj;
}

// conv2 per-edge logit (1 head over 256 ch) + segment max
__global__ void k_c2_logit(const int* __restrict__ ei, const float* __restrict__ eat,
                           const float* __restrict__ We, const float* __restrict__ att) {
    int e = (blockIdx.x * blockDim.x + threadIdx.x) >> 5;
    if (e >= EA) return;
    int lane = threadIdx.x & 31;
    int s, d; float ea;
    if (e < Ee) { s = ei[e]; d = ei[Ee + e]; ea = eat[e]; }
    else        { s = e - Ee; d = s; ea = g_loop[s]; }
    int c0 = lane * 8;
    float4 a0 = *(const float4*)&g_xl[s * HID + c0];
    float4 a1 = *(const float4*)&g_xl[s * HID + c0 + 4];
    float4 b0 = *(const float4*)&g_xr[d * HID + c0];
    float4 b1 = *(const float4*)&g_xr[d * HID + c0 + 4];
    float4 w0 = *(const float4*)&We[c0];
    float4 w1 = *(const float4*)&We[c0 + 4];
    float4 t0 = *(const float4*)&att[c0];
    float4 t1 = *(const float4*)&att[c0 + 4];
    float acc;
    acc  = lrelu(a0.x + b0.x + ea * w0.x) * t0.x;
    acc += lrelu(a0.y + b0.y + ea * w0.y) * t0.y;
    acc += lrelu(a0.z + b0.z + ea * w0.z) * t0.z;
    acc += lrelu(a0.w + b0.w + ea * w0.w) * t0.w;
    acc += lrelu(a1.x + b1.x + ea * w1.x) * t1.x;
    acc += lrelu(a1.y + b1.y + ea * w1.y) * t1.y;
    acc += lrelu(a1.z + b1.z + ea * w1.z) * t1.z;
    acc += lrelu(a1.w + b1.w + ea * w1.w) * t1.w;
    #pragma unroll
    for (int off = 16; off; off >>= 1) acc += __shfl_xor_sync(0xffffffffu, acc, off);
    if (lane == 0) {
        g_logit[e] = acc;
        atomicMax(&g_mx[d], fenc(acc));
    }
}

__global__ void k_c2_expsum(const int* __restrict__ ei) {
    int e = blockIdx.x * blockDim.x + threadIdx.x;
    if (e >= EA) return;
    int d = (e < Ee) ? ei[Ee + e] : e - Ee;
    float ex = __expf(g_logit[e] - fdec(g_mx[d]));
    g_logit[e] = ex;
    atomicAdd(&g_den[d], ex);
}

__global__ void k_c2_agg(const int* __restrict__ ei) {
    int e = (blockIdx.x * blockDim.x + threadIdx.x) >> 5;
    if (e >= EA) return;
    int lane = threadIdx.x & 31;
    int s, d;
    if (e < Ee) { s = ei[e]; d = ei[Ee + e]; }
    else        { s = e - Ee; d = s; }
    float alpha = g_logit[e] / g_den[d];
    int c0 = lane * 8;
    float4 a0 = *(const float4*)&g_xl[s * HID + c0];
    float4 a1 = *(const float4*)&g_xl[s * HID + c0 + 4];
    red4(&g_h2[d * HID + c0],     a0.x * alpha, a0.y * alpha, a0.z * alpha, a0.w * alpha);
    red4(&g_h2[d * HID + c0 + 4], a1.x * alpha, a1.y * alpha, a1.z * alpha, a1.w * alpha);
}

// policy head: relu(h2 @ Wp1 + bp1) @ Wp2 + bp2 -> g_plog, plus global max
__global__ void k_policy(const float* __restrict__ Wp1, const float* __restrict__ bp1,
                         const float* __restrict__ Wp2, const float* __restrict__ bp2) {
    __shared__ float sh[32][HID];          // 32 KB
    int i0 = blockIdx.x * 32;
    int t = threadIdx.x;                   // 128 threads
    for (int idx = t; idx < 32 * HID; idx += 128) {
        int r = idx >> 8, c = idx & 255;
        sh[r][c] = (i0 + r < Nn) ? g_h2[(i0 + r) * HID + c] : 0.f;
    }
    __syncthreads();
    float acc[32];
    #pragma unroll
    for (int i = 0; i < 32; i++) acc[i] = 0.f;
    for (int k = 0; k < HID; k += 4) {
        float w0 = Wp1[k * 128 + t];
        float w1 = Wp1[(k + 1) * 128 + t];
        float w2 = Wp1[(k + 2) * 128 + t];
        float w3 = Wp1[(k + 3) * 128 + t];
        #pragma unroll
        for (int i = 0; i < 32; i++) {
            float4 hv = *(const float4*)&sh[i][k];
            acc[i] += hv.x * w0 + hv.y * w1 + hv.z * w2 + hv.w * w3;
        }
    }
    float b = bp1[t];
    __syncthreads();                       // done reading sh; reuse as p1 (padded 129)
    float* p1 = &sh[0][0];
    #pragma unroll
    for (int i = 0; i < 32; i++) p1[i * 129 + t] = fmaxf(acc[i] + b, 0.f);
    __syncthreads();
    int node = t >> 2, c = t & 3;
    float s = bp2[c];
    for (int j = 0; j < 128; j++) s += p1[node * 129 + j] * Wp2[j * 4 + c];
    bool valid = (i0 + node) < Nn;
    if (valid) g_plog[(i0 + node) * 4 + c] = s;
    unsigned int m = valid ? fenc(s) : 0u;
    #pragma unroll
    for (int off = 16; off; off >>= 1) m = max(m, __shfl_xor_sync(0xffffffffu, m, off));
    if ((t & 31) == 0) atomicMax(&g_gmax, m);
}

// global softmax pass 1: exp + block-reduced sum
__global__ void k_sm1() {
    int idx = blockIdx.x * blockDim.x + threadIdx.x;
    float gm = fdec(g_gmax);
    float ex = 0.f;
    if (idx < Nn * 4) {
        ex = __expf(g_plog[idx] - gm);
        g_plog[idx] = ex;
    }
    #pragma unroll
    for (int off = 16; off; off >>= 1) ex += __shfl_xor_sync(0xffffffffu, ex, off);
    __shared__ float ws[8];
    if ((threadIdx.x & 31) == 0) ws[threadIdx.x >> 5] = ex;
    __syncthreads();
    if (threadIdx.x == 0) {
        float tot = 0.f;
        #pragma unroll
        for (int k = 0; k < 8; k++) tot += ws[k];
        atomicAdd(&g_gsum, tot);
    }
}

__global__ void k_sm2(float* __restrict__ out) {
    int idx = blockIdx.x * blockDim.x + threadIdx.x;
    if (idx < Nn * 4) out[idx] = g_plog[idx] / g_gsum;
}

// ---------------- host ------------------------------------------------------
extern "C" void kernel_launch(void* const* d_in, const int* in_sizes, int n_in,
                              void* d_out, int out_size) {
    const float* x    = (const float*)d_in[0];
    const int*   ei   = (const int*)  d_in[1];
    const float* eat  = (const float*)d_in[2];
    const float* Wl1  = (const float*)d_in[3];
    const float* bl1  = (const float*)d_in[4];
    const float* Wr1  = (const float*)d_in[5];
    const float* br1  = (const float*)d_in[6];
    const float* We1  = (const float*)d_in[7];
    const float* att1 = (const float*)d_in[8];
    const float* bias1= (const float*)d_in[9];
    const float* g1   = (const float*)d_in[10];
    const float* be1  = (const float*)d_in[11];
    const float* Wl2  = (const float*)d_in[12];
    const float* bl2  = (const float*)d_in[13];
    const float* Wr2  = (const float*)d_in[14];
    const float* br2  = (const float*)d_in[15];
    const float* We2  = (const float*)d_in[16];
    const float* att2 = (const float*)d_in[17];
    const float* bias2= (const float*)d_in[18];
    const float* g2   = (const float*)d_in[19];
    const float* be2  = (const float*)d_in[20];
    const float* Wp1  = (const float*)d_in[21];
    const float* bp1  = (const float*)d_in[22];
    const float* Wp2  = (const float*)d_in[23];
    const float* bp2  = (const float*)d_in[24];
    float* out = (float*)d_out;

    void *p_h, *p_h2, *p_deg, *p_loop, *p_mx, *p_den, *p_gmax, *p_gsum;
    cudaGetSymbolAddress(&p_h,    g_h);
    cudaGetSymbolAddress(&p_h2,   g_h2);
    cudaGetSymbolAddress(&p_deg,  g_deg);
    cudaGetSymbolAddress(&p_loop, g_loop);
    cudaGetSymbolAddress(&p_mx,   g_mx);
    cudaGetSymbolAddress(&p_den,  g_den);
    cudaGetSymbolAddress(&p_gmax, g_gmax);
    cudaGetSymbolAddress(&p_gsum, g_gsum);

    cudaMemsetAsync(p_deg,  0, Nn * sizeof(float));
    cudaMemsetAsync(p_loop, 0, Nn * sizeof(float));
    cudaMemsetAsync(p_mx,   0, Nn * 4 * sizeof(unsigned int));
    cudaMemsetAsync(p_den,  0, Nn * 4 * sizeof(float));
    cudaMemsetAsync(p_h,    0, (size_t)Nn * HID * sizeof(float));
    cudaMemsetAsync(p_h2,   0, (size_t)Nn * HID * sizeof(float));
    cudaMemsetAsync(p_gmax, 0, sizeof(unsigned int));
    cudaMemsetAsync(p_gsum, 0, sizeof(float));

    // self-loop attr
    k_deg<<<(Ee + 255) / 256, 256>>>(ei, eat);
    k_loopdiv<<<(Nn + 255) / 256, 256>>>();

    // conv1
    k_lin1<<<(Nn * HID + 255) / 256, 256>>>(x, Wl1, bl1, Wr1, br1);
    k_c1_logit<<<(EA + 7) / 8, 256>>>(ei, eat, We1, att1);
    k_c1_expsum<<<(EA * 4 + 255) / 256, 256>>>(ei);
    k_c1_agg<<<(EA + 7) / 8, 256>>>(ei);
    k_ln_relu<<<(Nn + 7) / 8, 256>>>((const float*)p_h, (float*)p_h, bias1, g1, be1);

    // conv2 linears (into g_xl / g_xr)
    k_gemm<<<dim3((Nn + 31) / 32, 2), 256>>>((const float*)p_h, Wl2, bl2, Wr2, br2);

    // conv2 attention (reuse mx/den first Nn entries)
    cudaMemsetAsync(p_mx,  0, Nn * sizeof(unsigned int));
    cudaMemsetAsync(p_den, 0, Nn * sizeof(float));
    k_c2_logit<<<(EA + 7) / 8, 256>>>(ei, eat, We2, att2);
    k_c2_expsum<<<(EA + 255) / 256, 256>>>(ei);
    k_c2_agg<<<(EA + 7) / 8, 256>>>(ei);
    k_ln_relu<<<(Nn + 7) / 8, 256>>>((const float*)p_h2, (float*)p_h2, bias2, g2, be2);

    // policy head + global softmax
    k_policy<<<(Nn + 31) / 32, 128>>>(Wp1, bp1, Wp2, bp2);
    k_sm1<<<(Nn * 4 + 255) / 256, 256>>>();
    k_sm2<<<(Nn * 4 + 255) / 256, 256>>>(out);
}

// round 2
// speedup vs baseline: 1.8474x; 1.8474x over previous
#include <cuda_runtime.h>

#define Nn 10000
#define Ee 320000
#define EA (Ee + Nn)
#define HID 256

// ---------------- scratch (static device globals; no allocations) ----------
__device__ __align__(16) float g_xl[Nn * HID];
__device__ __align__(16) float g_xr[Nn * HID];
__device__ __align__(16) float g_h [Nn * HID];
__device__ __align__(16) float g_h2[Nn * HID];
__device__ int          g_cnt[Nn];
__device__ int          g_cur[Nn];
__device__ int          g_rowptr[Nn + 1];
__device__ int          g_csrc[EA];
__device__ float        g_cea[EA];
__device__ float        g_loop[Nn];
__device__ float        g_plog[Nn * 4];
__device__ unsigned int g_gmax;
__device__ float        g_gsum;

// ---------------- helpers ---------------------------------------------------
__device__ __forceinline__ unsigned int fenc(float x) {
    unsigned int u = __float_as_uint(x);
    return (u & 0x80000000u) ? ~u : (u | 0x80000000u);
}
__device__ __forceinline__ float fdec(unsigned int e) {
    return __uint_as_float((e & 0x80000000u) ? (e & 0x7FFFFFFFu) : ~e);
}
__device__ __forceinline__ float lrelu(float x) { return x > 0.f ? x : 0.2f * x; }

// ---------------- CSR build --------------------------------------------------

// degree count + loop-attr sum
__global__ void k_deg(const int* __restrict__ ei, const float* __restrict__ eat) {
    int e = blockIdx.x * blockDim.x + threadIdx.x;
    if (e >= Ee) return;
    int d = ei[Ee + e];
    atomicAdd(&g_cnt[d], 1);
    atomicAdd(&g_loop[d], eat[e]);
}

__global__ void k_loopdiv() {
    int i = blockIdx.x * blockDim.x + threadIdx.x;
    if (i < Nn) g_loop[i] /= fmaxf((float)g_cnt[i], 1.0f);
}

// exclusive scan of (cnt[i]+1) -> rowptr.  Single block, 1024 threads x 10.
__global__ void k_scan() {
    __shared__ int part[1024];
    int t = threadIdx.x;
    int base = t * 10;
    int local[10];
    int s = 0;
    #pragma unroll
    for (int k = 0; k < 10; k++) {
        int idx = base + k;
        int v = (idx < Nn) ? (g_cnt[idx] + 1) : 0;
        local[k] = s;
        s += v;
    }
    part[t] = s;
    __syncthreads();
    for (int off = 1; off < 1024; off <<= 1) {
        int v = (t >= off) ? part[t - off] : 0;
        __syncthreads();
        part[t] += v;
        __syncthreads();
    }
    int offset = t ? part[t - 1] : 0;
    #pragma unroll
    for (int k = 0; k < 10; k++) {
        int idx = base + k;
        if (idx < Nn) g_rowptr[idx] = offset + local[k];
    }
    if (t == 1023) g_rowptr[Nn] = part[1023];
}

__global__ void k_scatter(const int* __restrict__ ei, const float* __restrict__ eat) {
    int e = blockIdx.x * blockDim.x + threadIdx.x;
    if (e >= Ee) return;
    int d = ei[Ee + e];
    int pos = g_rowptr[d] + atomicAdd(&g_cur[d], 1);
    g_csrc[pos] = ei[e];
    g_cea[pos]  = eat[e];
}

__global__ void k_selfloop() {
    int i = blockIdx.x * blockDim.x + threadIdx.x;
    if (i >= Nn) return;
    int pos = g_rowptr[i + 1] - 1;
    g_csrc[pos] = i;
    g_cea[pos]  = g_loop[i];
}

// ---------------- conv1 ------------------------------------------------------

// conv1 linear: x [N,4] @ W [4,256] + b  -> g_xl / g_xr
__global__ void k_lin1(const float* __restrict__ x,
                       const float* __restrict__ Wl, const float* __restrict__ bl,
                       const float* __restrict__ Wr, const float* __restrict__ br) {
    int idx = blockIdx.x * blockDim.x + threadIdx.x;
    if (idx >= Nn * HID) return;
    int i = idx >> 8, j = idx & 255;
    float x0 = x[i * 4], x1 = x[i * 4 + 1], x2 = x[i * 4 + 2], x3 = x[i * 4 + 3];
    g_xl[idx] = x0 * Wl[j] + x1 * Wl[256 + j] + x2 * Wl[512 + j] + x3 * Wl[768 + j] + bl[j];
    g_xr[idx] = x0 * Wr[j] + x1 * Wr[256 + j] + x2 * Wr[512 + j] + x3 * Wr[768 + j] + br[j];
}

// Fused conv1: one warp per dst node, online softmax over its edge segment.
// 4 heads; lanes [8h, 8h+8) handle head h (8 channels each).
__global__ void k_conv1(const float* __restrict__ We, const float* __restrict__ att) {
    int node = (blockIdx.x * blockDim.x + threadIdx.x) >> 5;
    if (node >= Nn) return;
    int lane = threadIdx.x & 31;
    int c0 = lane * 8;
    float4 b0 = *(const float4*)&g_xr[node * HID + c0];
    float4 b1 = *(const float4*)&g_xr[node * HID + c0 + 4];
    float4 w0 = *(const float4*)&We[c0];
    float4 w1 = *(const float4*)&We[c0 + 4];
    float4 t0 = *(const float4*)&att[c0];
    float4 t1 = *(const float4*)&att[c0 + 4];
    float mx = -3.4e38f, den = 0.f;
    float4 acc0 = {0, 0, 0, 0}, acc1 = {0, 0, 0, 0};
    int j0 = g_rowptr[node], j1 = g_rowptr[node + 1];
    int s = g_csrc[j0];
    float ea = g_cea[j0];
    for (int j = j0; j < j1; j++) {
        int s_n = 0; float ea_n = 0.f;
        if (j + 1 < j1) { s_n = g_csrc[j + 1]; ea_n = g_cea[j + 1]; }
        float4 a0 = *(const float4*)&g_xl[s * HID + c0];
        float4 a1 = *(const float4*)&g_xl[s * HID + c0 + 4];
        float p;
        p  = lrelu(a0.x + b0.x + ea * w0.x) * t0.x;
        p += lrelu(a0.y + b0.y + ea * w0.y) * t0.y;
        p += lrelu(a0.z + b0.z + ea * w0.z) * t0.z;
        p += lrelu(a0.w + b0.w + ea * w0.w) * t0.w;
        p += lrelu(a1.x + b1.x + ea * w1.x) * t1.x;
        p += lrelu(a1.y + b1.y + ea * w1.y) * t1.y;
        p += lrelu(a1.z + b1.z + ea * w1.z) * t1.z;
        p += lrelu(a1.w + b1.w + ea * w1.w) * t1.w;
        p += __shfl_xor_sync(0xffffffffu, p, 1);
        p += __shfl_xor_sync(0xffffffffu, p, 2);
        p += __shfl_xor_sync(0xffffffffu, p, 4);
        float nm = fmaxf(mx, p);
        float sc = __expf(mx - nm);
        float pe = __expf(p - nm);
        den = den * sc + pe;
        acc0.x = acc0.x * sc + pe * a0.x;
        acc0.y = acc0.y * sc + pe * a0.y;
        acc0.z = acc0.z * sc + pe * a0.z;
        acc0.w = acc0.w * sc + pe * a0.w;
        acc1.x = acc1.x * sc + pe * a1.x;
        acc1.y = acc1.y * sc + pe * a1.y;
        acc1.z = acc1.z * sc + pe * a1.z;
        acc1.w = acc1.w * sc + pe * a1.w;
        mx = nm;
        s = s_n; ea = ea_n;
    }
    float inv = 1.0f / den;
    float4 o0, o1;
    o0.x = acc0.x * inv; o0.y = acc0.y * inv; o0.z = acc0.z * inv; o0.w = acc0.w * inv;
    o1.x = acc1.x * inv; o1.y = acc1.y * inv; o1.z = acc1.z * inv; o1.w = acc1.w * inv;
    *(float4*)&g_h[node * HID + c0]     = o0;
    *(float4*)&g_h[node * HID + c0 + 4] = o1;
}

// Fused conv2: one warp per dst node, 1 head over 256 channels.
__global__ void k_conv2(const float* __restrict__ We, const float* __restrict__ att) {
    int node = (blockIdx.x * blockDim.x + threadIdx.x) >> 5;
    if (node >= Nn) return;
    int lane = threadIdx.x & 31;
    int c0 = lane * 8;
    float4 b0 = *(const float4*)&g_xr[node * HID + c0];
    float4 b1 = *(const float4*)&g_xr[node * HID + c0 + 4];
    float4 w0 = *(const float4*)&We[c0];
    float4 w1 = *(const float4*)&We[c0 + 4];
    float4 t0 = *(const float4*)&att[c0];
    float4 t1 = *(const float4*)&att[c0 + 4];
    float mx = -3.4e38f, den = 0.f;
    float4 acc0 = {0, 0, 0, 0}, acc1 = {0, 0, 0, 0};
    int j0 = g_rowptr[node], j1 = g_rowptr[node + 1];
    int s = g_csrc[j0];
    float ea = g_cea[j0];
    for (int j = j0; j < j1; j++) {
        int s_n = 0; float ea_n = 0.f;
        if (j + 1 < j1) { s_n = g_csrc[j + 1]; ea_n = g_cea[j + 1]; }
        float4 a0 = *(const float4*)&g_xl[s * HID + c0];
        float4 a1 = *(const float4*)&g_xl[s * HID + c0 + 4];
        float p;
        p  = lrelu(a0.x + b0.x + ea * w0.x) * t0.x;
        p += lrelu(a0.y + b0.y + ea * w0.y) * t0.y;
        p += lrelu(a0.z + b0.z + ea * w0.z) * t0.z;
        p += lrelu(a0.w + b0.w + ea * w0.w) * t0.w;
        p += lrelu(a1.x + b1.x + ea * w1.x) * t1.x;
        p += lrelu(a1.y + b1.y + ea * w1.y) * t1.y;
        p += lrelu(a1.z + b1.z + ea * w1.z) * t1.z;
        p += lrelu(a1.w + b1.w + ea * w1.w) * t1.w;
        #pragma unroll
        for (int off = 16; off; off >>= 1) p += __shfl_xor_sync(0xffffffffu, p, off);
        float nm = fmaxf(mx, p);
        float sc = __expf(mx - nm);
        float pe = __expf(p - nm);
        den = den * sc + pe;
        acc0.x = acc0.x * sc + pe * a0.x;
        acc0.y = acc0.y * sc + pe * a0.y;
        acc0.z = acc0.z * sc + pe * a0.z;
        acc0.w = acc0.w * sc + pe * a0.w;
        acc1.x = acc1.x * sc + pe * a1.x;
        acc1.y = acc1.y * sc + pe * a1.y;
        acc1.z = acc1.z * sc + pe * a1.z;
        acc1.w = acc1.w * sc + pe * a1.w;
        mx = nm;
        s = s_n; ea = ea_n;
    }
    float inv = 1.0f / den;
    float4 o0, o1;
    o0.x = acc0.x * inv; o0.y = acc0.y * inv; o0.z = acc0.z * inv; o0.w = acc0.w * inv;
    o1.x = acc1.x * inv; o1.y = acc1.y * inv; o1.z = acc1.z * inv; o1.w = acc1.w * inv;
    *(float4*)&g_h2[node * HID + c0]     = o0;
    *(float4*)&g_h2[node * HID + c0 + 4] = o1;
}

// layernorm(in + bias) * g + b, then relu.  One warp per node.
__global__ void k_ln_relu(const float* __restrict__ inp, float* __restrict__ outp,
                          const float* __restrict__ bias, const float* __restrict__ gam,
                          const float* __restrict__ bet) {
    int w = (blockIdx.x * blockDim.x + threadIdx.x) >> 5;
    if (w >= Nn) return;
    int lane = threadIdx.x & 31, c0 = lane * 8;
    float v[8];
    float4 p0 = *(const float4*)&inp[w * HID + c0];
    float4 p1 = *(const float4*)&inp[w * HID + c0 + 4];
    float4 q0 = *(const float4*)&bias[c0];
    float4 q1 = *(const float4*)&bias[c0 + 4];
    v[0] = p0.x + q0.x; v[1] = p0.y + q0.y; v[2] = p0.z + q0.z; v[3] = p0.w + q0.w;
    v[4] = p1.x + q1.x; v[5] = p1.y + q1.y; v[6] = p1.z + q1.z; v[7] = p1.w + q1.w;
    float s = 0.f;
    #pragma unroll
    for (int k = 0; k < 8; k++) s += v[k];
    #pragma unroll
    for (int off = 16; off; off >>= 1) s += __shfl_xor_sync(0xffffffffu, s, off);
    float mu = s * (1.0f / HID);
    float q = 0.f;
    #pragma unroll
    for (int k = 0; k < 8; k++) { float t = v[k] - mu; q += t * t; }
    #pragma unroll
    for (int off = 16; off; off >>= 1) q += __shfl_xor_sync(0xffffffffu, q, off);
    float r = rsqrtf(q * (1.0f / HID) + 1e-5f);
    float4 go0 = *(const float4*)&gam[c0];
    float4 go1 = *(const float4*)&gam[c0 + 4];
    float4 bo0 = *(const float4*)&bet[c0];
    float4 bo1 = *(const float4*)&bet[c0 + 4];
    float4 o0, o1;
    o0.x = fmaxf((v[0] - mu) * r * go0.x + bo0.x, 0.f);
    o0.y = fmaxf((v[1] - mu) * r * go0.y + bo0.y, 0.f);
    o0.z = fmaxf((v[2] - mu) * r * go0.z + bo0.z, 0.f);
    o0.w = fmaxf((v[3] - mu) * r * go0.w + bo0.w, 0.f);
    o1.x = fmaxf((v[4] - mu) * r * go1.x + bo1.x, 0.f);
    o1.y = fmaxf((v[5] - mu) * r * go1.y + bo1.y, 0.f);
    o1.z = fmaxf((v[6] - mu) * r * go1.z + bo1.z, 0.f);
    o1.w = fmaxf((v[7] - mu) * r * go1.w + bo1.w, 0.f);
    *(float4*)&outp[w * HID + c0]     = o0;
    *(float4*)&outp[w * HID + c0 + 4] = o1;
}

// conv2 linears: g_h [N,256] @ W [256,256] + b -> g_xl (y=0) / g_xr (y=1)
__global__ void k_gemm(const float* __restrict__ Hin,
                       const float* __restrict__ W0, const float* __restrict__ b0,
                       const float* __restrict__ W1, const float* __restrict__ b1) {
    __shared__ float sh[32][HID];
    const float* W  = blockIdx.y ? W1 : W0;
    const float* bb = blockIdx.y ? b1 : b0;
    float* O        = blockIdx.y ? g_xr : g_xl;
    int i0 = blockIdx.x * 32;
    int t = threadIdx.x;
    for (int idx = t; idx < 32 * HID; idx += 256) {
        int r = idx >> 8, c = idx & 255;
        sh[r][c] = (i0 + r < Nn) ? Hin[(i0 + r) * HID + c] : 0.f;
    }
    __syncthreads();
    float acc[32];
    #pragma unroll
    for (int i = 0; i < 32; i++) acc[i] = 0.f;
    for (int k = 0; k < HID; k += 4) {
        float w0 = W[k * HID + t];
        float w1 = W[(k + 1) * HID + t];
        float w2 = W[(k + 2) * HID + t];
        float w3 = W[(k + 3) * HID + t];
        #pragma unroll
        for (int i = 0; i < 32; i++) {
            float4 hv = *(const float4*)&sh[i][k];
            acc[i] += hv.x * w0 + hv.y * w1 + hv.z * w2 + hv.w * w3;
        }
    }
    float bj = bb[t];
    #pragma unroll
    for (int i = 0; i < 32; i++)
        if (i0 + i < Nn) O[(i0 + i) * HID + t] = acc[i] + bj;
}

// policy head: relu(h2 @ Wp1 + bp1) @ Wp2 + bp2 -> g_plog, plus global max
__global__ void k_policy(const float* __restrict__ Wp1, const float* __restrict__ bp1,
                         const float* __restrict__ Wp2, const float* __restrict__ bp2) {
    __shared__ float sh[32][HID];
    int i0 = blockIdx.x * 32;
    int t = threadIdx.x;                   // 128 threads
    for (int idx = t; idx < 32 * HID; idx += 128) {
        int r = idx >> 8, c = idx & 255;
        sh[r][c] = (i0 + r < Nn) ? g_h2[(i0 + r) * HID + c] : 0.f;
    }
    __syncthreads();
    float acc[32];
    #pragma unroll
    for (int i = 0; i < 32; i++) acc[i] = 0.f;
    for (int k = 0; k < HID; k += 4) {
        float w0 = Wp1[k * 128 + t];
        float w1 = Wp1[(k + 1) * 128 + t];
        float w2 = Wp1[(k + 2) * 128 + t];
        float w3 = Wp1[(k + 3) * 128 + t];
        #pragma unroll
        for (int i = 0; i < 32; i++) {
            float4 hv = *(const float4*)&sh[i][k];
            acc[i] += hv.x * w0 + hv.y * w1 + hv.z * w2 + hv.w * w3;
        }
    }
    float b = bp1[t];
    __syncthreads();
    float* p1 = &sh[0][0];
    #pragma unroll
    for (int i = 0; i < 32; i++) p1[i * 129 + t] = fmaxf(acc[i] + b, 0.f);
    __syncthreads();
    int node = t >> 2, c = t & 3;
    float s = bp2[c];
    for (int j = 0; j < 128; j++) s += p1[node * 129 + j] * Wp2[j * 4 + c];
    bool valid = (i0 + node) < Nn;
    if (valid) g_plog[(i0 + node) * 4 + c] = s;
    unsigned int m = valid ? fenc(s) : 0u;
    #pragma unroll
    for (int off = 16; off; off >>= 1) m = max(m, __shfl_xor_sync(0xffffffffu, m, off));
    if ((t & 31) == 0) atomicMax(&g_gmax, m);
}

__global__ void k_sm1() {
    int idx = blockIdx.x * blockDim.x + threadIdx.x;
    float gm = fdec(g_gmax);
    float ex = 0.f;
    if (idx < Nn * 4) {
        ex = __expf(g_plog[idx] - gm);
        g_plog[idx] = ex;
    }
    #pragma unroll
    for (int off = 16; off; off >>= 1) ex += __shfl_xor_sync(0xffffffffu, ex, off);
    __shared__ float ws[8];
    if ((threadIdx.x & 31) == 0) ws[threadIdx.x >> 5] = ex;
    __syncthreads();
    if (threadIdx.x == 0) {
        float tot = 0.f;
        #pragma unroll
        for (int k = 0; k < 8; k++) tot += ws[k];
        atomicAdd(&g_gsum, tot);
    }
}

__global__ void k_sm2(float* __restrict__ out) {
    int idx = blockIdx.x * blockDim.x + threadIdx.x;
    if (idx < Nn * 4) out[idx] = g_plog[idx] / g_gsum;
}

// ---------------- host ------------------------------------------------------
extern "C" void kernel_launch(void* const* d_in, const int* in_sizes, int n_in,
                              void* d_out, int out_size) {
    const float* x    = (const float*)d_in[0];
    const int*   ei   = (const int*)  d_in[1];
    const float* eat  = (const float*)d_in[2];
    const float* Wl1  = (const float*)d_in[3];
    const float* bl1  = (const float*)d_in[4];
    const float* Wr1  = (const float*)d_in[5];
    const float* br1  = (const float*)d_in[6];
    const float* We1  = (const float*)d_in[7];
    const float* att1 = (const float*)d_in[8];
    const float* bias1= (const float*)d_in[9];
    const float* g1   = (const float*)d_in[10];
    const float* be1  = (const float*)d_in[11];
    const float* Wl2  = (const float*)d_in[12];
    const float* bl2  = (const float*)d_in[13];
    const float* Wr2  = (const float*)d_in[14];
    const float* br2  = (const float*)d_in[15];
    const float* We2  = (const float*)d_in[16];
    const float* att2 = (const float*)d_in[17];
    const float* bias2= (const float*)d_in[18];
    const float* g2   = (const float*)d_in[19];
    const float* be2  = (const float*)d_in[20];
    const float* Wp1  = (const float*)d_in[21];
    const float* bp1  = (const float*)d_in[22];
    const float* Wp2  = (const float*)d_in[23];
    const float* bp2  = (const float*)d_in[24];
    float* out = (float*)d_out;

    void *p_h, *p_h2, *p_cnt, *p_cur, *p_loop, *p_gmax, *p_gsum;
    cudaGetSymbolAddress(&p_h,    g_h);
    cudaGetSymbolAddress(&p_h2,   g_h2);
    cudaGetSymbolAddress(&p_cnt,  g_cnt);
    cudaGetSymbolAddress(&p_cur,  g_cur);
    cudaGetSymbolAddress(&p_loop, g_loop);
    cudaGetSymbolAddress(&p_gmax, g_gmax);
    cudaGetSymbolAddress(&p_gsum, g_gsum);

    cudaMemsetAsync(p_cnt,  0, Nn * sizeof(int));
    cudaMemsetAsync(p_cur,  0, Nn * sizeof(int));
    cudaMemsetAsync(p_loop, 0, Nn * sizeof(float));
    cudaMemsetAsync(p_gmax, 0, sizeof(unsigned int));
    cudaMemsetAsync(p_gsum, 0, sizeof(float));

    // CSR build
    k_deg<<<(Ee + 255) / 256, 256>>>(ei, eat);
    k_loopdiv<<<(Nn + 255) / 256, 256>>>();
    k_scan<<<1, 1024>>>();
    k_scatter<<<(Ee + 255) / 256, 256>>>(ei, eat);
    k_selfloop<<<(Nn + 255) / 256, 256>>>();

    // conv1
    k_lin1<<<(Nn * HID + 255) / 256, 256>>>(x, Wl1, bl1, Wr1, br1);
    k_conv1<<<(Nn + 7) / 8, 256>>>(We1, att1);
    k_ln_relu<<<(Nn + 7) / 8, 256>>>((const float*)p_h, (float*)p_h, bias1, g1, be1);

    // conv2
    k_gemm<<<dim3((Nn + 31) / 32, 2), 256>>>((const float*)p_h, Wl2, bl2, Wr2, br2);
    k_conv2<<<(Nn + 7) / 8, 256>>>(We2, att2);
    k_ln_relu<<<(Nn + 7) / 8, 256>>>((const float*)p_h2, (float*)p_h2, bias2, g2, be2);

    // policy head + global softmax
    k_policy<<<(Nn + 31) / 32, 128>>>(Wp1, bp1, Wp2, bp2);
    k_sm1<<<(Nn * 4 + 255) / 256, 256>>>();
    k_sm2<<<(Nn * 4 + 255) / 256, 256>>>(out);
}